// round 17
// baseline (speedup 1.0000x reference)
#include <cuda_runtime.h>
#include <cuda_bf16.h>
#include <math.h>
#include <stdint.h>

#define BB   8
#define SS   1024
#define DD   512
#define HH   8
#define WW   8
#define S2S  1040
#define DKK  64

// ================= helpers =================
__device__ __forceinline__ uint32_t smem_u32(const void* p) {
    uint32_t a;
    asm("{ .reg .u64 t; cvta.to.shared.u64 t, %1; cvt.u32.u64 %0, t; }" : "=r"(a) : "l"(p));
    return a;
}
#define CP_A16(dst, src) \
    asm volatile("cp.async.cg.shared.global [%0], [%1], 16;" :: "r"((uint32_t)(dst)), "l"(src))
#define CP_COMMIT() asm volatile("cp.async.commit_group;" ::: "memory")
#define CP_WAIT(n)  asm volatile("cp.async.wait_group %0;" :: "n"(n) : "memory")

__device__ __forceinline__ void ldsm_x4(uint32_t& r0, uint32_t& r1, uint32_t& r2, uint32_t& r3, uint32_t addr) {
    asm volatile("ldmatrix.sync.aligned.m8n8.x4.shared.b16 {%0,%1,%2,%3}, [%4];"
                 : "=r"(r0), "=r"(r1), "=r"(r2), "=r"(r3) : "r"(addr));
}
__device__ __forceinline__ void mma16816(float* d, const uint32_t* a, const uint32_t* b) {
    asm volatile("mma.sync.aligned.m16n8k16.row.col.f32.bf16.bf16.f32 "
                 "{%0,%1,%2,%3}, {%4,%5,%6,%7}, {%8,%9}, {%0,%1,%2,%3};"
                 : "+f"(d[0]), "+f"(d[1]), "+f"(d[2]), "+f"(d[3])
                 : "r"(a[0]), "r"(a[1]), "r"(a[2]), "r"(a[3]), "r"(b[0]), "r"(b[1]));
}
__device__ __forceinline__ void split2(float x, __nv_bfloat16& h, __nv_bfloat16& l) {
    h = __float2bfloat16(x);
    l = __float2bfloat16(x - __bfloat162float(h));
}

// ================= scratch (device globals) =================
#define DW   (DD * DD)
#define DW2  (DD * 2 * DD)
#define HWO  (8 * DW)
__device__ float g_nin[BB * S2S * DD];
__device__ __nv_bfloat16 g_ninh[BB * S2S * DD];
__device__ __nv_bfloat16 g_ninl[BB * S2S * DD];
__device__ float g_qkv[BB * S2S * 6 * DD];                // fused QKV output (lda=3072)
__device__ float g_bqkv[6 * DD];
__device__ float g_bhw[4 * 2 * DD];                       // interleaved hw biases
__device__ __nv_bfloat16 g_a0h[BB * SS * DD], g_a0l[BB * SS * DD];
__device__ __nv_bfloat16 g_a1h[BB * SS * DD], g_a1l[BB * SS * DD];
__device__ float g_hx0[BB * SS * DD], g_hx1[BB * SS * DD];
__device__ __nv_bfloat16 g_hx0h[BB * SS * DD], g_hx0l[BB * SS * DD];
__device__ __nv_bfloat16 g_hx1h[BB * SS * DD], g_hx1l[BB * SS * DD];
__device__ __nv_bfloat16 g_hy0h[BB * SS * DD], g_hy0l[BB * SS * DD];
__device__ __nv_bfloat16 g_hy1h[BB * SS * DD], g_hy1l[BB * SS * DD];
__device__ __nv_bfloat16 g_wth[8 * DW + 4 * DW2];
__device__ __nv_bfloat16 g_wtl[8 * DW + 4 * DW2];

// ================= single prep launch: wsplit + bias pack + new_in =========
#define PREP_W    4096
#define PREP_B    28
#define PREP_N    16640
__global__ void prep_all(const float* __restrict__ lW, const float* __restrict__ rW,
                         const float* __restrict__ lhW, const float* __restrict__ rhW,
                         const float* __restrict__ lb, const float* __restrict__ rb,
                         const float* __restrict__ lhb, const float* __restrict__ rhb,
                         const float* __restrict__ x, const float* __restrict__ lp,
                         const float* __restrict__ rp) {
    __shared__ float tile[32][33];
    int blk = blockIdx.x;
    int tid = threadIdx.x;
    if (blk < PREP_W) {
        const float* W;
        __nv_bfloat16 *th, *tl;
        int nb, kb, N;
        bool hw = false;
        if (blk < 2048) {
            int mat = blk >> 8;          // 0..7
            int t = blk & 255;
            N = 512;
            nb = (t & 15) * 32; kb = (t >> 4) * 32;
            int slot;
            if (mat < 4) { W = lW + (size_t)mat * DW; slot = (mat < 3) ? mat : 6; }
            else         { int i = mat - 4; W = rW + (size_t)i * DW; slot = (i < 3) ? 3 + i : 7; }
            th = g_wth + (size_t)slot * DW;
            tl = g_wtl + (size_t)slot * DW;
        } else {
            hw = true;
            int bb = blk - 2048;
            int mat = bb >> 9;           // 0..3  (lh0, lh1, rh0, rh1)
            int t = bb & 511;
            N = 1024;
            nb = (t & 31) * 32; kb = (t >> 5) * 32;
            W = (mat < 2) ? lhW + (size_t)mat * DW2 : rhW + (size_t)(mat - 2) * DW2;
            th = g_wth + HWO + (size_t)mat * DW2;
            tl = g_wtl + HWO + (size_t)mat * DW2;
        }
        int tx = tid & 31, ty = tid >> 5;
        for (int r = ty; r < 32; r += 8)
            tile[r][tx] = W[(size_t)(kb + r) * N + nb + tx];
        __syncthreads();
        for (int r = ty; r < 32; r += 8) {
            float v = tile[tx][r];
            __nv_bfloat16 h, l; split2(v, h, l);
            int nrow = nb + r;
            int p = hw ? ((nrow < DD) ? 2 * nrow : 2 * (nrow - DD) + 1) : nrow;
            size_t o = (size_t)p * 512 + kb + tx;
            th[o] = h; tl[o] = l;
        }
    } else if (blk < PREP_W + PREP_B) {
        int n = (blk - PREP_W) * 256 + tid;
        if (n < 6 * DD) {
            int slot = n >> 9, loc = n & 511;
            g_bqkv[n] = (slot < 3) ? lb[slot * DD + loc] : rb[(slot - 3) * DD + loc];
        } else if (n < 6 * DD + 4 * 2 * DD) {
            int j = n - 6 * DD;
            int mat = j >> 10, p = j & 1023;
            int orig = (p & 1) ? DD + (p >> 1) : (p >> 1);
            g_bhw[mat * 2 * DD + p] = (mat < 2) ? lhb[mat * 2 * DD + orig]
                                                : rhb[(mat - 2) * 2 * DD + orig];
        }
    } else {
        int idx = (blk - PREP_W - PREP_B) * 256 + tid;
        int d = idx & (DD - 1);
        int t = idx >> 9;
        int s = t % S2S;
        int b = t / S2S;
        float val;
        if (s < WW)            val = lp[s * DD + d];
        else if (s < WW + SS)  val = x[((size_t)(b * SS + (s - WW))) * DD + d];
        else                   val = rp[(s - WW - SS) * DD + d];
        g_nin[idx] = val;
        __nv_bfloat16 h, l; split2(val, h, l);
        g_ninh[idx] = h; g_ninl[idx] = l;
    }
}

// fused-QKV banded attention; blockIdx.z = dir. i-fastest warp mapping.
__global__ void banded_attn_f(const float* __restrict__ qkv,
                              __nv_bfloat16* __restrict__ o0h, __nv_bfloat16* __restrict__ o0l,
                              __nv_bfloat16* __restrict__ o1h, __nv_bfloat16* __restrict__ o1l) {
    int dir = blockIdx.z;
    __nv_bfloat16* oh = dir ? o1h : o0h;
    __nv_bfloat16* ol = dir ? o1l : o0l;
    int qoff = dir * 3 * DD;
    int gw = (blockIdx.x * blockDim.x + threadIdx.x) >> 5;
    if (gw >= BB * SS * HH) return;
    int lane = threadIdx.x & 31;
    int i = gw & (SS - 1);
    int h = (gw >> 10) & (HH - 1);
    int b = gw >> 13;
    int qi = i + WW;
    int jlo, jhi;
    if (dir == 0) { jlo = qi - (WW + 1); if (jlo < 0) jlo = 0; jhi = qi; }
    else          { jlo = qi; jhi = qi + (WW + 1); if (jhi > S2S - 1) jhi = S2S - 1; }

    const int LDA = 6 * DD;
    const float* qp = qkv + ((size_t)(b * S2S + qi)) * LDA + qoff + h * DKK;
    float q0 = qp[lane], q1 = qp[lane + 32];

    float sc[WW + 2];
#pragma unroll
    for (int jj = 0; jj < WW + 2; jj++) {
        int j = jlo + jj;
        bool valid = (j <= jhi);
        int jc = valid ? j : jlo;
        const float* kp = qkv + ((size_t)(b * S2S + jc)) * LDA + qoff + DD + h * DKK;
        float s = q0 * kp[lane] + q1 * kp[lane + 32];
#pragma unroll
        for (int o = 16; o; o >>= 1) s += __shfl_xor_sync(0xffffffffu, s, o);
        sc[jj] = valid ? s * 0.125f : -1e30f;
    }
    float m = sc[0];
#pragma unroll
    for (int jj = 1; jj < WW + 2; jj++) m = fmaxf(m, sc[jj]);
    float sum = 0.f;
#pragma unroll
    for (int jj = 0; jj < WW + 2; jj++) { sc[jj] = expf(sc[jj] - m); sum += sc[jj]; }
    float inv = 1.f / sum;
    float o0 = 0.f, o1 = 0.f;
#pragma unroll
    for (int jj = 0; jj < WW + 2; jj++) {
        int j = jlo + jj;
        int jc = (j <= jhi) ? j : jlo;
        const float* vp = qkv + ((size_t)(b * S2S + jc)) * LDA + qoff + 2 * DD + h * DKK;
        o0 += sc[jj] * vp[lane];
        o1 += sc[jj] * vp[lane + 32];
    }
    size_t op = ((size_t)(b * SS + i)) * DD + h * DKK;
    __nv_bfloat16 hh, ll;
    split2(o0 * inv, hh, ll); oh[op + lane] = hh; ol[op + lane] = ll;
    split2(o1 * inv, hh, ll); oh[op + lane + 32] = hh; ol[op + lane + 32] = ll;
}

// ================= fused split-bf16 GEMM with fused epilogues ==============
// mainloop unchanged from R15 (3-stage dist-2, de-phased circular K, 3 sweeps).
// mode-2 epilogue stages the 136x128 nin window tile in smem; row stride 132
// floats (528 B, 16B-aligned for float4 stores), 71.8KB <= 96KB.
#define KK     512
#define NCK    16                      // KK/32
#define TILEB  (128 * 64)              // 8192 B per tile (128 rows x 64 B)
#define STG4   (4 * TILEB)             // 32768 B per stage
#define GSMEM3 (3 * STG4)              // 98304 B
#define SWZOFF(row, chunk) ((uint32_t)((row) * 64 + (((chunk) ^ (((row) >> 1) & 3)) << 4)))
#define NINP   132                     // padded smem row stride (floats, 16B-aligned rows)

struct GArg {
    const __nv_bfloat16 *ah, *al, *bh, *bl;
    const float* bias;
    float* c;
    const float* xin;          // mode 1
    const float* relw;         // mode 2
    __nv_bfloat16 *dh, *dl;    // modes 1,2 (optional in 1)
    int mode, base, lddc;
};

__global__ __launch_bounds__(256, 2) void gemm3(
    GArg ga0, GArg ga1, int M, int N)
{
    extern __shared__ char smem[];
    uint32_t sb = smem_u32(smem);
    const GArg g = blockIdx.z ? ga1 : ga0;
    const int tid = threadIdx.x, wid = tid >> 5, lane = tid & 31;
    const int row0 = blockIdx.y * 128, col0 = blockIdx.x * 128;
    const int wm = (wid >> 2) * 64;      // 0 or 64
    const int wn = (wid & 3) * 32;       // 0,32,64,96

    // de-phase co-resident CTAs: start circular K loop at chunk 0 or 8
    const int c0 = ((blockIdx.x + blockIdx.y + blockIdx.z) & 1) * (NCK / 2);

    // ---- load-side precompute (affine in kb) ----
    const int lr = tid >> 2, lkc = tid & 3;
    const uint32_t s0 = SWZOFF(lr, lkc);
    const uint32_t s1 = SWZOFF(lr + 64, lkc);
    const uint32_t aIdx0 = (uint32_t)(row0 + lr) * (uint32_t)KK + lkc * 8;
    const uint32_t aIdx1 = aIdx0 + (uint32_t)(64 * KK);
    const uint32_t bIdx0 = (uint32_t)(col0 + lr) * (uint32_t)KK + lkc * 8;
    const uint32_t bIdx1 = bIdx0 + (uint32_t)(64 * KK);

    // ---- compute-side ldsm offsets (loop-invariant; ks=1 -> ^32) ----
    uint32_t offA[4], offB[2];
#pragma unroll
    for (int im = 0; im < 4; im++) {
        int row = wm + im * 16 + (lane & 15);
        offA[im] = SWZOFF(row, (lane >> 4));
    }
    {
        int m = lane >> 3;
#pragma unroll
        for (int p = 0; p < 2; p++) {
            int row = wn + (2 * p + (m >> 1)) * 8 + (lane & 7);
            offB[p] = SWZOFF(row, (m & 1));
        }
    }

#define KB_OF(t) ((uint32_t)(((t) + c0) & (NCK - 1)) << 5)
#define LOAD_STAGE(st, kb) do {                                        \
        uint32_t _b = sb + (uint32_t)(st) * STG4;                      \
        uint32_t _k = (uint32_t)(kb);                                  \
        CP_A16(_b + s0,             g.ah + aIdx0 + _k);                \
        CP_A16(_b + s1,             g.ah + aIdx1 + _k);                \
        CP_A16(_b + TILEB + s0,     g.al + aIdx0 + _k);                \
        CP_A16(_b + TILEB + s1,     g.al + aIdx1 + _k);                \
        CP_A16(_b + 2 * TILEB + s0, g.bh + bIdx0 + _k);                \
        CP_A16(_b + 2 * TILEB + s1, g.bh + bIdx1 + _k);                \
        CP_A16(_b + 3 * TILEB + s0, g.bl + bIdx0 + _k);                \
        CP_A16(_b + 3 * TILEB + s1, g.bl + bIdx1 + _k);                \
        CP_COMMIT();                                                   \
    } while (0)

    LOAD_STAGE(0, KB_OF(0));
    LOAD_STAGE(1, KB_OF(1));

    float d[16][4];
#pragma unroll
    for (int i = 0; i < 16; i++)
#pragma unroll
        for (int j = 0; j < 4; j++) d[i][j] = 0.f;

    int st = 0;
    for (int t = 0; t < NCK; t++) {
        if (t + 1 < NCK) { CP_WAIT(1); } else { CP_WAIT(0); }
        __syncthreads();                 // all threads' group-t data visible
        if (t + 2 < NCK) {
            int st2 = st + 2; if (st2 >= 3) st2 -= 3;
            LOAD_STAGE(st2, KB_OF(t + 2));
        } else {
            CP_COMMIT();                 // keep group count consistent
        }
        uint32_t abh = sb + (uint32_t)st * STG4;
        uint32_t abl = abh + TILEB;
        uint32_t bbh = abh + 2 * TILEB;
        uint32_t bbl = abh + 3 * TILEB;
#pragma unroll
        for (int ks = 0; ks < 2; ks++) {
            const uint32_t kx = (uint32_t)(ks << 5);
            uint32_t ah[4][4], al[4][4], bh[4][2], bl[4][2];
#pragma unroll
            for (int im = 0; im < 4; im++) {
                uint32_t off = offA[im] ^ kx;
                ldsm_x4(ah[im][0], ah[im][1], ah[im][2], ah[im][3], abh + off);
                ldsm_x4(al[im][0], al[im][1], al[im][2], al[im][3], abl + off);
            }
#pragma unroll
            for (int p = 0; p < 2; p++) {
                uint32_t off = offB[p] ^ kx;
                ldsm_x4(bh[2 * p][0], bh[2 * p][1], bh[2 * p + 1][0], bh[2 * p + 1][1], bbh + off);
                ldsm_x4(bl[2 * p][0], bl[2 * p][1], bl[2 * p + 1][0], bl[2 * p + 1][1], bbl + off);
            }
            // three sweeps: accumulator reuse spaced by 15 independent MMAs;
            // per-accumulator order is still bh -> bl -> al*bh (FP-identical)
#pragma unroll
            for (int im = 0; im < 4; im++)
#pragma unroll
                for (int in = 0; in < 4; in++)
                    mma16816(d[im * 4 + in], ah[im], bh[in]);
#pragma unroll
            for (int im = 0; im < 4; im++)
#pragma unroll
                for (int in = 0; in < 4; in++)
                    mma16816(d[im * 4 + in], ah[im], bl[in]);
#pragma unroll
            for (int im = 0; im < 4; im++)
#pragma unroll
                for (int in = 0; in < 4; in++)
                    mma16816(d[im * 4 + in], al[im], bh[in]);
        }
        st++; if (st >= 3) st = 0;
    }
#undef LOAD_STAGE
#undef KB_OF

    // ================= epilogues =================
    if (g.mode == 0) {
#pragma unroll
        for (int im = 0; im < 4; im++)
#pragma unroll
            for (int in = 0; in < 4; in++) {
                float* dd = d[im * 4 + in];
                int m = row0 + wm + im * 16 + (lane >> 2);
                int n = col0 + wn + in * 8 + ((lane & 3) << 1);
                float b0 = g.bias[n], b1 = g.bias[n + 1];
                *(float2*)&g.c[(size_t)m * N + n] = make_float2(dd[0] + b0, dd[1] + b1);
                *(float2*)&g.c[(size_t)(m + 8) * N + n] = make_float2(dd[2] + b0, dd[3] + b1);
            }
    } else if (g.mode == 2) {
        // stage the 136x128 nin window tile in smem (mainloop smem is dead)
        __syncthreads();
        float* snin = (float*)smem;
        const int bq = row0 >> 10;           // batch (row0 = bq*1024 + i0)
        const int i0 = row0 & 1023;
        const float* src = g_nin + ((size_t)(bq * S2S + g.base + i0)) * DD + col0;
        for (int v = tid; v < 136 * 32; v += 256) {
            int r = v >> 5, c4 = (v & 31) << 2;
            *(float4*)&snin[r * NINP + c4] = *(const float4*)(src + (size_t)r * DD + c4);
        }
        __syncthreads();
        float w[WW + 1];
#pragma unroll
        for (int j = 0; j <= WW; j++) w[j] = g.relw[j];
#pragma unroll
        for (int im = 0; im < 4; im++)
#pragma unroll
            for (int in = 0; in < 4; in++) {
                float* dd = d[im * 4 + in];
                int lr0 = wm + im * 16 + (lane >> 2);     // local row in [0,128)
                int m = row0 + lr0;
                int lc = wn + in * 8 + ((lane & 3) << 1); // local col in [0,128)
                int n = col0 + lc;
                float b0 = g.bias[n], b1 = g.bias[n + 1];
                float y0 = dd[0] + b0, y1 = dd[1] + b1;
                float y2 = dd[2] + b0, y3 = dd[3] + b1;
#pragma unroll
                for (int j = 0; j <= WW; j++) {
                    float2 v = *(const float2*)&snin[(lr0 + j) * NINP + lc];
                    float2 v2 = *(const float2*)&snin[(lr0 + 8 + j) * NINP + lc];
                    y0 += w[j] * v.x;  y1 += w[j] * v.y;
                    y2 += w[j] * v2.x; y3 += w[j] * v2.y;
                }
                *(float2*)&g.c[(size_t)m * DD + n] = make_float2(y0, y1);
                *(float2*)&g.c[(size_t)(m + 8) * DD + n] = make_float2(y2, y3);
                __nv_bfloat16 h0, l0, h1, l1;
                split2(y0, h0, l0); split2(y1, h1, l1);
                *(__nv_bfloat162*)&g.dh[(size_t)m * DD + n] = __nv_bfloat162(h0, h1);
                *(__nv_bfloat162*)&g.dl[(size_t)m * DD + n] = __nv_bfloat162(l0, l1);
                split2(y2, h0, l0); split2(y3, h1, l1);
                *(__nv_bfloat162*)&g.dh[(size_t)(m + 8) * DD + n] = __nv_bfloat162(h0, h1);
                *(__nv_bfloat162*)&g.dl[(size_t)(m + 8) * DD + n] = __nv_bfloat162(l0, l1);
            }
    } else {  // mode 1: highway gate
#pragma unroll
        for (int im = 0; im < 4; im++)
#pragma unroll
            for (int in = 0; in < 4; in++) {
                float* dd = d[im * 4 + in];
                int m = row0 + wm + im * 16 + (lane >> 2);
                int n = col0 + wn + in * 8 + ((lane & 3) << 1);
                int u = n >> 1;
                float b0 = g.bias[n], b1 = g.bias[n + 1];
                float nl0 = fmaxf(dd[0] + b0, 0.f);
                float gz0 = dd[1] + b1;
                float nl1 = fmaxf(dd[2] + b0, 0.f);
                float gz1 = dd[3] + b1;
                float x0 = g.xin[(size_t)m * DD + u];
                float x1 = g.xin[(size_t)(m + 8) * DD + u];
                float s0g = 1.f / (1.f + expf(-gz0));
                float s1g = 1.f / (1.f + expf(-gz1));
                float y0 = s0g * x0 + (1.f - s0g) * nl0;
                float y1 = s1g * x1 + (1.f - s1g) * nl1;
                g.c[(size_t)m * g.lddc + u] = y0;
                g.c[(size_t)(m + 8) * g.lddc + u] = y1;
                if (g.dh) {
                    __nv_bfloat16 h, l;
                    split2(y0, h, l);
                    g.dh[(size_t)m * DD + u] = h; g.dl[(size_t)m * DD + u] = l;
                    split2(y1, h, l);
                    g.dh[(size_t)(m + 8) * DD + u] = h; g.dl[(size_t)(m + 8) * DD + u] = l;
                }
            }
    }
}

// ================= launch =================
extern "C" void kernel_launch(void* const* d_in, const int* in_sizes, int n_in,
                              void* d_out, int out_size)
{
    const float* x    = (const float*)d_in[0];
    const float* lW   = (const float*)d_in[1];
    const float* lb   = (const float*)d_in[2];
    const float* rW   = (const float*)d_in[3];
    const float* rb   = (const float*)d_in[4];
    const float* lpad = (const float*)d_in[5];
    const float* rpad = (const float*)d_in[6];
    const float* lw   = (const float*)d_in[7];
    const float* rw   = (const float*)d_in[8];
    const float* lhW  = (const float*)d_in[9];
    const float* lhb  = (const float*)d_in[10];
    const float* rhW  = (const float*)d_in[11];
    const float* rhb  = (const float*)d_in[12];
    float* out = (float*)d_out;

    cudaFuncSetAttribute(gemm3, cudaFuncAttributeMaxDynamicSharedMemorySize, GSMEM3);

    float *qkv, *bqkv, *bhw, *hx0, *hx1;
    __nv_bfloat16 *ninh, *ninl, *a0h, *a0l, *a1h, *a1l;
    __nv_bfloat16 *hx0h, *hx0l, *hx1h, *hx1l;
    __nv_bfloat16 *hy0h, *hy0l, *hy1h, *hy1l, *wth, *wtl;
    cudaGetSymbolAddress((void**)&qkv, g_qkv);
    cudaGetSymbolAddress((void**)&bqkv, g_bqkv);
    cudaGetSymbolAddress((void**)&bhw, g_bhw);
    cudaGetSymbolAddress((void**)&hx0, g_hx0); cudaGetSymbolAddress((void**)&hx1, g_hx1);
    cudaGetSymbolAddress((void**)&ninh, g_ninh); cudaGetSymbolAddress((void**)&ninl, g_ninl);
    cudaGetSymbolAddress((void**)&a0h, g_a0h); cudaGetSymbolAddress((void**)&a0l, g_a0l);
    cudaGetSymbolAddress((void**)&a1h, g_a1h); cudaGetSymbolAddress((void**)&a1l, g_a1l);
    cudaGetSymbolAddress((void**)&hx0h, g_hx0h); cudaGetSymbolAddress((void**)&hx0l, g_hx0l);
    cudaGetSymbolAddress((void**)&hx1h, g_hx1h); cudaGetSymbolAddress((void**)&hx1l, g_hx1l);
    cudaGetSymbolAddress((void**)&hy0h, g_hy0h); cudaGetSymbolAddress((void**)&hy0l, g_hy0l);
    cudaGetSymbolAddress((void**)&hy1h, g_hy1h); cudaGetSymbolAddress((void**)&hy1l, g_hy1l);
    cudaGetSymbolAddress((void**)&wth, g_wth); cudaGetSymbolAddress((void**)&wtl, g_wtl);

    // all prep in one launch
    prep_all<<<PREP_W + PREP_B + PREP_N, 256>>>(lW, rW, lhW, rhW, lb, rb, lhb, rhb,
                                                x, lpad, rpad);

    // fused QKV: M=8320, N=3072, K=512 (mode 0)
    {
        GArg a = {ninh, ninl, wth, wtl, bqkv, qkv,
                  nullptr, nullptr, nullptr, nullptr, 0, 0, 0};
        gemm3<<<dim3(24, 65, 1), 256, GSMEM3>>>(a, a, BB * S2S, 6 * DD);
    }

    // banded attention (both dirs)
    banded_attn_f<<<dim3((BB * SS * HH * 32) / 256, 1, 2), 256>>>(qkv, a0h, a0l, a1h, a1l);

    // output projections + fused rel-add (mode 2)
    {
        GArg p0 = {a0h, a0l, wth + 6 * (size_t)DW, wtl + 6 * (size_t)DW, lb + 3 * DD, hx0,
                   nullptr, lw, hx0h, hx0l, 2, 0, DD};
        GArg p1 = {a1h, a1l, wth + 7 * (size_t)DW, wtl + 7 * (size_t)DW, rb + 3 * DD, hx1,
                   nullptr, rw, hx1h, hx1l, 2, WW, DD};
        gemm3<<<dim3(4, 64, 2), 256, GSMEM3>>>(p0, p1, BB * SS, DD);
    }

    // highway layer 1 (mode 1, gate fused)
    {
        GArg h0 = {hx0h, hx0l, wth + HWO, wtl + HWO, bhw + 0, hx0,
                   hx0, nullptr, hy0h, hy0l, 1, 0, DD};
        GArg h1 = {hx1h, hx1l, wth + HWO + 2 * (size_t)DW2, wtl + HWO + 2 * (size_t)DW2, bhw + 2 * 2 * DD, hx1,
                   hx1, nullptr, hy1h, hy1l, 1, 0, DD};
        gemm3<<<dim3(8, 64, 2), 256, GSMEM3>>>(h0, h1, BB * SS, 2 * DD);
    }
    // highway layer 2 (mode 1) -> strided output
    {
        GArg h0 = {hy0h, hy0l, wth + HWO + (size_t)DW2, wtl + HWO + (size_t)DW2, bhw + 1 * 2 * DD, out + 0,
                   hx0, nullptr, nullptr, nullptr, 1, 0, 2 * DD};
        GArg h1 = {hy1h, hy1l, wth + HWO + 3 * (size_t)DW2, wtl + HWO + 3 * (size_t)DW2, bhw + 3 * 2 * DD, out + DD,
                   hx1, nullptr, nullptr, nullptr, 1, 0, 2 * DD};
        gemm3<<<dim3(8, 64, 2), 256, GSMEM3>>>(h0, h1, BB * SS, 2 * DD);
    }
}